// round 5
// baseline (speedup 1.0000x reference)
#include <cuda_runtime.h>

typedef unsigned long long ull;

#define RR 256
#define CC 32
#define SS 8
#define HH 32
#define WARPS 4
#define FPAD 36

__constant__ float cW0[CC*HH], cW1[HH*HH], cCW0[CC*HH], cCW1[HH*HH];
__constant__ float cB0[HH], cB1[HH], cCB0[HH], cCB1[HH];
__constant__ float cWOUT[HH], cCWOUT[HH*3];
__constant__ float cBND[SS*6];
__constant__ float cBO[1], cCBO[3];

// shared memory: per-warp param block + two feat transpose buffers
#define SM_PAR    0                              // WARPS*32*16 = 2048 words
#define SM_FEATA  (SM_PAR + WARPS*32*16)         // WARPS*32*FPAD
#define SM_FEATB  (SM_FEATA + WARPS*32*FPAD)
#define SMEM_FLOATS (SM_FEATB + WARPS*32*FPAD)   // 2048 + 2*4608 = 11264 w = 45056 B

__device__ __forceinline__ ull pack2(float lo, float hi) {
    ull d; asm("mov.b64 %0, {%1, %2};" : "=l"(d) : "f"(lo), "f"(hi)); return d;
}
__device__ __forceinline__ void unpack2(ull v, float& lo, float& hi) {
    asm("mov.b64 {%0, %1}, %2;" : "=f"(lo), "=f"(hi) : "l"(v));
}
__device__ __forceinline__ void fma2(ull& d, ull a, ull b) {
    asm("fma.rn.f32x2 %0, %1, %2, %0;" : "+l"(d) : "l"(a), "l"(b));
}

// layer with smem source row (feat -> h)
#define LAYER32S(row, W, B, h)                                             \
    do {                                                                   \
        _Pragma("unroll")                                                  \
        for (int j = 0; j < 8; j++) {                                      \
            const ulonglong2 bv = *(const ulonglong2*)&B[j * 4];           \
            h[2*j] = bv.x; h[2*j+1] = bv.y;                                \
        }                                                                  \
        _Pragma("unroll")                                                  \
        for (int i4 = 0; i4 < 8; i4++) {                                   \
            const float4 f4 = *(const float4*)&(row)[i4 * 4];              \
            const float fk[4] = { f4.x, f4.y, f4.z, f4.w };                \
            _Pragma("unroll")                                              \
            for (int k = 0; k < 4; k++) {                                  \
                const ull a = pack2(fk[k], fk[k]);                         \
                _Pragma("unroll")                                          \
                for (int j = 0; j < 8; j++) {                              \
                    const ulonglong2 w =                                   \
                        *(const ulonglong2*)&W[(i4 * 4 + k) * HH + j * 4]; \
                    fma2(h[2*j],   a, w.x);                                \
                    fma2(h[2*j+1], a, w.y);                                \
                }                                                          \
            }                                                              \
        }                                                                  \
    } while (0)

// layer with register source: input = relu(h1), packed pairs (h1 -> h2)
#define LAYER32R(h1, W, B, h2)                                             \
    do {                                                                   \
        _Pragma("unroll")                                                  \
        for (int j = 0; j < 8; j++) {                                      \
            const ulonglong2 bv = *(const ulonglong2*)&B[j * 4];           \
            h2[2*j] = bv.x; h2[2*j+1] = bv.y;                              \
        }                                                                  \
        _Pragma("unroll")                                                  \
        for (int i = 0; i < 16; i++) {                                     \
            float fa, fb; unpack2(h1[i], fa, fb);                          \
            fa = fmaxf(fa, 0.0f); fb = fmaxf(fb, 0.0f);                    \
            const ull pa = pack2(fa, fa);                                  \
            const ull pb = pack2(fb, fb);                                  \
            _Pragma("unroll")                                              \
            for (int j = 0; j < 8; j++) {                                  \
                const ulonglong2 wa =                                      \
                    *(const ulonglong2*)&W[(2*i) * HH + j * 4];            \
                const ulonglong2 wb =                                      \
                    *(const ulonglong2*)&W[(2*i+1) * HH + j * 4];          \
                fma2(h2[2*j],   pa, wa.x);                                 \
                fma2(h2[2*j+1], pa, wa.y);                                 \
                fma2(h2[2*j],   pb, wb.x);                                 \
                fma2(h2[2*j+1], pb, wb.y);                                 \
            }                                                              \
        }                                                                  \
    } while (0)

__global__ __launch_bounds__(128, 5) void decoders_kernel(
    const float* __restrict__ p,
    const float* __restrict__ pxy, const float* __restrict__ pxz, const float* __restrict__ pyz,
    const float* __restrict__ cxy, const float* __restrict__ cxz, const float* __restrict__ cyz,
    float* __restrict__ out, int n)
{
    extern __shared__ float smem[];
    const int tid = threadIdx.x;
    const int warp = tid >> 5, lane = tid & 31;
    const int base = (blockIdx.x * WARPS + warp) * 32;
    float* __restrict__ par = smem + SM_PAR   + warp * (32 * 16);
    float* __restrict__ sfA = smem + SM_FEATA + warp * (32 * FPAD);
    float* __restrict__ sfB = smem + SM_FEATB + warp * (32 * FPAD);

    // ---- per-lane params for point base+lane ----
    {
        const int idx = base + lane;
        float px = 2.0f, py = 2.0f, pz = 2.0f;
        if (idx < n) { px = p[idx*3]; py = p[idx*3+1]; pz = p[idx*3+2]; }

        int s = 0; bool valid = false;
        #pragma unroll
        for (int k = SS - 1; k >= 0; k--) {
            const float lx = cBND[k*6+0], ly = cBND[k*6+1], lz = cBND[k*6+2];
            const float hx = cBND[k*6+3], hy = cBND[k*6+4], hz = cBND[k*6+5];
            const bool in = (px > lx) & (px < hx) & (py > ly) & (py < hy) & (pz > lz) & (pz < hz);
            if (in) { s = k; valid = true; }
        }
        const float m = valid ? 1.0f : 0.0f;

        const float bx0 = cBND[s*6+0], by0 = cBND[s*6+1], bz0 = cBND[s*6+2];
        const float bx1 = cBND[s*6+3], by1 = cBND[s*6+4], bz1 = cBND[s*6+5];
        const float pnx = (px - bx0) / (bx1 - bx0) * 2.0f - 1.0f;
        const float pny = (py - by0) / (by1 - by0) * 2.0f - 1.0f;
        const float pnz = (pz - bz0) / (bz1 - bz0) * 2.0f - 1.0f;

        const float us[3] = { pnx, pnx, pny };
        const float vs[3] = { pny, pnz, pnz };
        #pragma unroll
        for (int t = 0; t < 3; t++) {
            const float x = (us[t] + 1.0f) * 0.5f * (float)(RR - 1);
            const float y = (vs[t] + 1.0f) * 0.5f * (float)(RR - 1);
            const float xf = fminf(fmaxf(floorf(x), 0.0f), (float)(RR - 2));
            const float yf = fminf(fmaxf(floorf(y), 0.0f), (float)(RR - 2));
            const float wx = x - xf, wy = y - yf;
            float4 q;
            q.x = m * (1.0f - wx) * (1.0f - wy);
            q.y = m * wx * (1.0f - wy);
            q.z = m * (1.0f - wx) * wy;
            q.w = m * wx * wy;
            *(float4*)&par[lane * 16 + t * 4] = q;
            const int off = ((s * RR + (int)yf) * RR + (int)xf) * CC;
            ((int*)par)[lane * 16 + 12 + t] = off;
        }
    }
    __syncwarp();

    // ---- fused gather: both branches share offsets & weights ----
    #pragma unroll 4
    for (int pt = 0; pt < 32; pt++) {
        const float4 q0 = *(const float4*)&par[pt * 16 + 0];
        const float4 q1 = *(const float4*)&par[pt * 16 + 4];
        const float4 q2 = *(const float4*)&par[pt * 16 + 8];
        const int4  qo = *(const int4*) &par[pt * 16 + 12];
        const float* a = pxy + qo.x + lane;
        const float* b = pxz + qo.y + lane;
        const float* c = pyz + qo.z + lane;
        const float* d = cxy + qo.x + lane;
        const float* e = cxz + qo.y + lane;
        const float* f = cyz + qo.z + lane;
        float fA, fB;
        fA  = q0.x * a[0] + q0.y * a[CC] + q0.z * a[RR*CC] + q0.w * a[RR*CC + CC];
        fA += q1.x * b[0] + q1.y * b[CC] + q1.z * b[RR*CC] + q1.w * b[RR*CC + CC];
        fA += q2.x * c[0] + q2.y * c[CC] + q2.z * c[RR*CC] + q2.w * c[RR*CC + CC];
        fB  = q0.x * d[0] + q0.y * d[CC] + q0.z * d[RR*CC] + q0.w * d[RR*CC + CC];
        fB += q1.x * e[0] + q1.y * e[CC] + q1.z * e[RR*CC] + q1.w * e[RR*CC + CC];
        fB += q2.x * f[0] + q2.y * f[CC] + q2.z * f[RR*CC] + q2.w * f[RR*CC + CC];
        sfA[pt * FPAD + lane] = fA;
        sfB[pt * FPAD + lane] = fB;
    }
    __syncwarp();

    ull h1[16], h2[16];
    const float* __restrict__ rowA = sfA + lane * FPAD;
    const float* __restrict__ rowB = sfB + lane * FPAD;

    // ================= SDF branch =================
    LAYER32S(rowA, cW0, cB0, h1);
    LAYER32R(h1, cW1, cB1, h2);
    float sdf;
    {
        float acc = cBO[0];
        #pragma unroll
        for (int j = 0; j < 16; j++) {
            float a, b; unpack2(h2[j], a, b);
            acc += fmaxf(a, 0.0f) * cWOUT[2*j];
            acc += fmaxf(b, 0.0f) * cWOUT[2*j + 1];
        }
        sdf = tanhf(acc);
    }

    // ================= Color branch =================
    LAYER32S(rowB, cCW0, cCB0, h1);
    LAYER32R(h1, cCW1, cCB1, h2);

    float rA = cCBO[0], gA = cCBO[1], bA = cCBO[2];
    #pragma unroll
    for (int j = 0; j < 16; j++) {
        float a, b; unpack2(h2[j], a, b);
        const float ha = fmaxf(a, 0.0f), hb = fmaxf(b, 0.0f);
        rA += ha * cCWOUT[(2*j)*3 + 0] + hb * cCWOUT[(2*j+1)*3 + 0];
        gA += ha * cCWOUT[(2*j)*3 + 1] + hb * cCWOUT[(2*j+1)*3 + 1];
        bA += ha * cCWOUT[(2*j)*3 + 2] + hb * cCWOUT[(2*j+1)*3 + 2];
    }

    const int idx = base + lane;
    if (idx < n) {
        float4 o;
        o.x = 1.0f / (1.0f + expf(-rA));
        o.y = 1.0f / (1.0f + expf(-gA));
        o.z = 1.0f / (1.0f + expf(-bA));
        o.w = sdf;
        ((float4*)out)[idx] = o;
    }
}

extern "C" void kernel_launch(void* const* d_in, const int* in_sizes, int n_in,
                              void* d_out, int out_size) {
    const float* p          = (const float*)d_in[0];
    const float* boundaries = (const float*)d_in[1];
    const float* pxy        = (const float*)d_in[2];
    const float* pxz        = (const float*)d_in[3];
    const float* pyz        = (const float*)d_in[4];
    const float* cxy        = (const float*)d_in[5];
    const float* cxz        = (const float*)d_in[6];
    const float* cyz        = (const float*)d_in[7];

    cudaMemcpyToSymbolAsync(cW0,    d_in[8],  CC*HH*4, 0, cudaMemcpyDeviceToDevice, 0);
    cudaMemcpyToSymbolAsync(cB0,    d_in[9],  HH*4,    0, cudaMemcpyDeviceToDevice, 0);
    cudaMemcpyToSymbolAsync(cW1,    d_in[10], HH*HH*4, 0, cudaMemcpyDeviceToDevice, 0);
    cudaMemcpyToSymbolAsync(cB1,    d_in[11], HH*4,    0, cudaMemcpyDeviceToDevice, 0);
    cudaMemcpyToSymbolAsync(cWOUT,  d_in[12], HH*4,    0, cudaMemcpyDeviceToDevice, 0);
    cudaMemcpyToSymbolAsync(cBO,    d_in[13], 4,       0, cudaMemcpyDeviceToDevice, 0);
    cudaMemcpyToSymbolAsync(cCW0,   d_in[14], CC*HH*4, 0, cudaMemcpyDeviceToDevice, 0);
    cudaMemcpyToSymbolAsync(cCB0,   d_in[15], HH*4,    0, cudaMemcpyDeviceToDevice, 0);
    cudaMemcpyToSymbolAsync(cCW1,   d_in[16], HH*HH*4, 0, cudaMemcpyDeviceToDevice, 0);
    cudaMemcpyToSymbolAsync(cCB1,   d_in[17], HH*4,    0, cudaMemcpyDeviceToDevice, 0);
    cudaMemcpyToSymbolAsync(cCWOUT, d_in[18], HH*3*4,  0, cudaMemcpyDeviceToDevice, 0);
    cudaMemcpyToSymbolAsync(cCBO,   d_in[19], 3*4,     0, cudaMemcpyDeviceToDevice, 0);
    cudaMemcpyToSymbolAsync(cBND,   boundaries, SS*6*4, 0, cudaMemcpyDeviceToDevice, 0);

    const int n = in_sizes[0] / 3;
    float* out = (float*)d_out;

    const int smem_bytes = SMEM_FLOATS * (int)sizeof(float);
    cudaFuncSetAttribute(decoders_kernel,
                         cudaFuncAttributeMaxDynamicSharedMemorySize, smem_bytes);

    const int pts_per_block = WARPS * 32;   // 128
    const int blocks = (n + pts_per_block - 1) / pts_per_block;
    decoders_kernel<<<blocks, 128, smem_bytes>>>(
        p, pxy, pxz, pyz, cxy, cxz, cyz, out, n);
}